// round 13
// baseline (speedup 1.0000x reference)
#include <cuda_runtime.h>
#include <cuda_bf16.h>

// loss[s] = -(1/496)*[ sum_i x_i*(31-i) - sum_{i<j} ln(e_i+e_j) + 0.0005*sum_i x_i^2*(31-2i) ]
// via log_sigmoid(x_i - x_j) == x_i - ln(e^{x_i} + e^{x_j}).
//
// sum_{pairs} ln = ln(prod): per lane ONE 16-term fp32 product of (e_i+e_j)/4
// terms (2^-2 prescale keeps the exponent in range; prescale correction and
// exponent bias fold into a single constant), one lg2 at the end.
//
// Scalar, 4 segments/warp as 4 independent chains, interleaved float2 rings
// (one LDS.64 feeds two chains). Lane reduction via select-exchange folding:
// the 4 per-lane partials merge into 1 register during the first two
// reduction steps, then a 3-step butterfly finishes.

static constexpr float INV_PAIRS = 1.0f / 496.0f;
static constexpr float LN2  = 0.69314718055994530942f;
static constexpr float L2E  = 1.44269504088896340736f;
static constexpr int   WPB  = 4;                 // warps per block (128 thr)
static constexpr int   SEG_PER_BLOCK = WPB * 4;  // 16

typedef unsigned int u32;

__device__ __forceinline__ float ex2(float x) {
    float r; asm("ex2.approx.f32 %0,%1;" : "=f"(r) : "f"(x)); return r;
}
__device__ __forceinline__ float lg2(float x) {
    float r; asm("lg2.approx.f32 %0,%1;" : "=f"(r) : "f"(x)); return r;
}

__global__ __launch_bounds__(WPB * 32)
void rmloss_kernel(const float* __restrict__ logits,
                   float* __restrict__ out,
                   int n_seg)
{
    __shared__ float2 r01[WPB][64];   // interleaved (seg0, seg1), duplicated ring
    __shared__ float2 r23[WPB][64];   // interleaved (seg2, seg3), duplicated ring

    const int w    = threadIdx.x >> 5;
    const int lane = threadIdx.x & 31;
    const int gw   = blockIdx.x * WPB + w;
    const int s0   = gw * 4;                        // 4 segments per warp
    if (s0 >= n_seg) return;

    const float* base = logits + (size_t)s0 * 32 + lane;
    const float x0 = base[0],  x1 = base[32];
    const float x2 = base[64], x3 = base[96];

    // e = exp(x) * 2^-2 = exp2(x*log2e - 2): prescale keeps the 16-term
    // product exponent-safe; correction folded into KPS below.
    const float e0 = ex2(fmaf(x0, L2E, -2.0f));
    const float e1 = ex2(fmaf(x1, L2E, -2.0f));
    const float e2 = ex2(fmaf(x2, L2E, -2.0f));
    const float e3 = ex2(fmaf(x3, L2E, -2.0f));

    // Duplicated interleaved rings -> pair reads are LDS.64 [base + imm].
    const float2 v01 = make_float2(e0, e1);
    const float2 v23 = make_float2(e2, e3);
    r01[w][lane] = v01;  r01[w][lane + 32] = v01;
    r23[w][lane] = v23;  r23[w][lane + 32] = v23;
    __syncwarp();

    // Single 16-term product per chain. Offsets 1..15 hit each unordered pair
    // exactly once; offset 16 only lanes 0..15 (upper half multiplies by 1).
    float2 a = r01[w][lane + 1], b = r23[w][lane + 1];
    float p0 = e0 + a.x, p1 = e1 + a.y, p2 = e2 + b.x, p3 = e3 + b.y;
    #pragma unroll
    for (int o = 2; o <= 15; ++o) {
        a = r01[w][lane + o];  b = r23[w][lane + o];
        p0 *= e0 + a.x;  p1 *= e1 + a.y;
        p2 *= e2 + b.x;  p3 *= e3 + b.y;
    }
    {
        a = r01[w][lane + 16];  b = r23[w][lane + 16];
        const bool m = (lane < 16);
        p0 *= m ? (e0 + a.x) : 1.0f;
        p1 *= m ? (e1 + a.y) : 1.0f;
        p2 *= m ? (e2 + b.x) : 1.0f;
        p3 *= m ? (e3 + b.y) : 1.0f;
    }

    // Constants (all scale factors folded):
    //   partial = x*CL + x^2*CQ + CLN*[E + lg2(m)] + KPS
    // KPS absorbs the -127 exponent bias and the 2^-2-per-term prescale.
    const float CL  = (float)(31 - lane)     * (-INV_PAIRS);
    const float CQ  = (float)(31 - 2 * lane) * (-0.0005f * INV_PAIRS);
    const float CLN = LN2 * INV_PAIRS;
    const float KPS = CLN * (((lane < 16) ? 32.0f : 30.0f) - 127.0f);

    const u32 b0 = __float_as_uint(p0), b1 = __float_as_uint(p1);
    const u32 b2 = __float_as_uint(p2), b3 = __float_as_uint(p3);
    const float m0 = __uint_as_float((b0 & 0x007FFFFFu) | 0x3F800000u);
    const float m1 = __uint_as_float((b1 & 0x007FFFFFu) | 0x3F800000u);
    const float m2 = __uint_as_float((b2 & 0x007FFFFFu) | 0x3F800000u);
    const float m3 = __uint_as_float((b3 & 0x007FFFFFu) | 0x3F800000u);

    float t0 = fmaf((float)(int)(b0 >> 23), CLN, KPS);
    float t1 = fmaf((float)(int)(b1 >> 23), CLN, KPS);
    float t2 = fmaf((float)(int)(b2 >> 23), CLN, KPS);
    float t3 = fmaf((float)(int)(b3 >> 23), CLN, KPS);
    t0 = fmaf(lg2(m0), CLN, t0);
    t1 = fmaf(lg2(m1), CLN, t1);
    t2 = fmaf(lg2(m2), CLN, t2);
    t3 = fmaf(lg2(m3), CLN, t3);

    t0 = fmaf(x0, CL, t0);  t0 = fmaf(x0 * x0, CQ, t0);
    t1 = fmaf(x1, CL, t1);  t1 = fmaf(x1 * x1, CQ, t1);
    t2 = fmaf(x2, CL, t2);  t2 = fmaf(x2 * x2, CQ, t2);
    t3 = fmaf(x3, CL, t3);  t3 = fmaf(x3 * x3, CQ, t3);

    // Select-exchange reduction: fold 4 values -> 1 during the first two
    // steps, then a 3-step butterfly inside 8-lane groups.
    // Step A (xor 16): lo half keeps (t0,t1) & receives hi's (t0,t1); hi
    // half symmetric with (t2,t3).
    const bool lo16b = (lane < 16);
    float ka = lo16b ? t0 : t2;
    float sa = lo16b ? t2 : t0;
    float u  = ka + __shfl_xor_sync(0xFFFFFFFFu, sa, 16);
    float kb = lo16b ? t1 : t3;
    float sb = lo16b ? t3 : t1;
    float v  = kb + __shfl_xor_sync(0xFFFFFFFFu, sb, 16);
    // Step B (xor 8): bit3=0 lanes keep u / send v; bit3=1 keep v / send u.
    const bool lo8 = (lane & 8) == 0;
    float kc = lo8 ? u : v;
    float sc = lo8 ? v : u;
    float s  = kc + __shfl_xor_sync(0xFFFFFFFFu, sc, 8);
    // Now group g = lane>>3 holds segment g's partial over its residue class.
    s += __shfl_xor_sync(0xFFFFFFFFu, s, 4);
    s += __shfl_xor_sync(0xFFFFFFFFu, s, 2);
    s += __shfl_xor_sync(0xFFFFFFFFu, s, 1);

    if ((lane & 7) == 0)
        out[s0 + (lane >> 3)] = s;      // lanes 0,8,16,24 -> 4 consecutive floats
}

extern "C" void kernel_launch(void* const* d_in, const int* in_sizes, int n_in,
                              void* d_out, int out_size)
{
    const float* logits = (const float*)d_in[0];
    float* out = (float*)d_out;
    const int n_seg = out_size;                  // 32768

    const int threads = WPB * 32;                // 128
    const int blocks = (n_seg + SEG_PER_BLOCK - 1) / SEG_PER_BLOCK;   // 2048
    rmloss_kernel<<<blocks, threads>>>(logits, out, n_seg);
}

// round 14
// speedup vs baseline: 1.0295x; 1.0295x over previous
#include <cuda_runtime.h>
#include <cuda_bf16.h>

// loss[s] = -(1/496)*[ sum_i x_i*(31-i) - sum_{i<j} ln(e_i+e_j) + 0.0005*sum_i x_i^2*(31-2i) ]
// via log_sigmoid(x_i - x_j) == x_i - ln(e^{x_i} + e^{x_j}).
//
// sum_{pairs} ln = ln(prod): per lane ONE 16-term fp32 product of (e_i+e_j)/4
// terms (2^-2 prescale keeps the exponent in range; prescale correction and
// exponent bias fold into a single constant), one lg2 at the end.
//
// Scalar, 4 segments/warp as 4 independent chains, interleaved float2 rings
// (one LDS.64 feeds two chains). Select-exchange reduction folds the 4
// per-lane partials into 1 register during the first two steps.
// 64-thread blocks x 4096 CTAs: finest scheduling granularity (best-benching
// launch shape across 13 measured rounds).

static constexpr float INV_PAIRS = 1.0f / 496.0f;
static constexpr float LN2  = 0.69314718055994530942f;
static constexpr float L2E  = 1.44269504088896340736f;
static constexpr int   WPB  = 2;                 // warps per block (64 thr)
static constexpr int   SEG_PER_BLOCK = WPB * 4;  // 8

typedef unsigned int u32;

__device__ __forceinline__ float ex2(float x) {
    float r; asm("ex2.approx.f32 %0,%1;" : "=f"(r) : "f"(x)); return r;
}
__device__ __forceinline__ float lg2(float x) {
    float r; asm("lg2.approx.f32 %0,%1;" : "=f"(r) : "f"(x)); return r;
}

__global__ __launch_bounds__(WPB * 32, 32)
void rmloss_kernel(const float* __restrict__ logits,
                   float* __restrict__ out,
                   int n_seg)
{
    __shared__ float2 r01[WPB][64];   // interleaved (seg0, seg1), duplicated ring
    __shared__ float2 r23[WPB][64];   // interleaved (seg2, seg3), duplicated ring

    const int w    = threadIdx.x >> 5;
    const int lane = threadIdx.x & 31;
    const int gw   = blockIdx.x * WPB + w;
    const int s0   = gw * 4;                        // 4 segments per warp
    if (s0 >= n_seg) return;

    const float* base = logits + (size_t)s0 * 32 + lane;
    const float x0 = base[0],  x1 = base[32];
    const float x2 = base[64], x3 = base[96];

    // e = exp(x) * 2^-2 = exp2(x*log2e - 2): prescale keeps the 16-term
    // product exponent-safe; correction folded into KPS below.
    const float e0 = ex2(fmaf(x0, L2E, -2.0f));
    const float e1 = ex2(fmaf(x1, L2E, -2.0f));
    const float e2 = ex2(fmaf(x2, L2E, -2.0f));
    const float e3 = ex2(fmaf(x3, L2E, -2.0f));

    // Duplicated interleaved rings -> pair reads are LDS.64 [base + imm].
    const float2 v01 = make_float2(e0, e1);
    const float2 v23 = make_float2(e2, e3);
    r01[w][lane] = v01;  r01[w][lane + 32] = v01;
    r23[w][lane] = v23;  r23[w][lane + 32] = v23;
    __syncwarp();

    // Single 16-term product per chain. Offsets 1..15 hit each unordered pair
    // exactly once; offset 16 only lanes 0..15 (upper half multiplies by 1).
    float2 a = r01[w][lane + 1], b = r23[w][lane + 1];
    float p0 = e0 + a.x, p1 = e1 + a.y, p2 = e2 + b.x, p3 = e3 + b.y;
    #pragma unroll
    for (int o = 2; o <= 15; ++o) {
        a = r01[w][lane + o];  b = r23[w][lane + o];
        p0 *= e0 + a.x;  p1 *= e1 + a.y;
        p2 *= e2 + b.x;  p3 *= e3 + b.y;
    }
    {
        a = r01[w][lane + 16];  b = r23[w][lane + 16];
        const bool m = (lane < 16);
        p0 *= m ? (e0 + a.x) : 1.0f;
        p1 *= m ? (e1 + a.y) : 1.0f;
        p2 *= m ? (e2 + b.x) : 1.0f;
        p3 *= m ? (e3 + b.y) : 1.0f;
    }

    // Constants (all scale factors folded):
    //   partial = x*CL + x^2*CQ + CLN*[E + lg2(m)] + KPS
    // KPS absorbs the -127 exponent bias and the 2^-2-per-term prescale.
    const float CL  = (float)(31 - lane)     * (-INV_PAIRS);
    const float CQ  = (float)(31 - 2 * lane) * (-0.0005f * INV_PAIRS);
    const float CLN = LN2 * INV_PAIRS;
    const float KPS = CLN * (((lane < 16) ? 32.0f : 30.0f) - 127.0f);

    const u32 b0 = __float_as_uint(p0), b1 = __float_as_uint(p1);
    const u32 b2 = __float_as_uint(p2), b3 = __float_as_uint(p3);
    const float m0 = __uint_as_float((b0 & 0x007FFFFFu) | 0x3F800000u);
    const float m1 = __uint_as_float((b1 & 0x007FFFFFu) | 0x3F800000u);
    const float m2 = __uint_as_float((b2 & 0x007FFFFFu) | 0x3F800000u);
    const float m3 = __uint_as_float((b3 & 0x007FFFFFu) | 0x3F800000u);

    float t0 = fmaf((float)(int)(b0 >> 23), CLN, KPS);
    float t1 = fmaf((float)(int)(b1 >> 23), CLN, KPS);
    float t2 = fmaf((float)(int)(b2 >> 23), CLN, KPS);
    float t3 = fmaf((float)(int)(b3 >> 23), CLN, KPS);
    t0 = fmaf(lg2(m0), CLN, t0);
    t1 = fmaf(lg2(m1), CLN, t1);
    t2 = fmaf(lg2(m2), CLN, t2);
    t3 = fmaf(lg2(m3), CLN, t3);

    t0 = fmaf(x0, CL, t0);  t0 = fmaf(x0 * x0, CQ, t0);
    t1 = fmaf(x1, CL, t1);  t1 = fmaf(x1 * x1, CQ, t1);
    t2 = fmaf(x2, CL, t2);  t2 = fmaf(x2 * x2, CQ, t2);
    t3 = fmaf(x3, CL, t3);  t3 = fmaf(x3 * x3, CQ, t3);

    // Select-exchange reduction: fold 4 values -> 1 during the first two
    // steps, then a 3-step butterfly inside 8-lane groups.
    // Step A (xor 16): lo half keeps (t0,t1) & receives hi's (t0,t1); hi
    // half symmetric with (t2,t3).
    const bool lo16b = (lane < 16);
    float ka = lo16b ? t0 : t2;
    float sa = lo16b ? t2 : t0;
    float u  = ka + __shfl_xor_sync(0xFFFFFFFFu, sa, 16);
    float kb = lo16b ? t1 : t3;
    float sb = lo16b ? t3 : t1;
    float v  = kb + __shfl_xor_sync(0xFFFFFFFFu, sb, 16);
    // Step B (xor 8): bit3=0 lanes keep u / send v; bit3=1 keep v / send u.
    const bool lo8 = (lane & 8) == 0;
    float kc = lo8 ? u : v;
    float sc = lo8 ? v : u;
    float s  = kc + __shfl_xor_sync(0xFFFFFFFFu, sc, 8);
    // Now group g = lane>>3 holds segment g's partial over its residue class.
    s += __shfl_xor_sync(0xFFFFFFFFu, s, 4);
    s += __shfl_xor_sync(0xFFFFFFFFu, s, 2);
    s += __shfl_xor_sync(0xFFFFFFFFu, s, 1);

    if ((lane & 7) == 0)
        out[s0 + (lane >> 3)] = s;      // lanes 0,8,16,24 -> 4 consecutive floats
}

extern "C" void kernel_launch(void* const* d_in, const int* in_sizes, int n_in,
                              void* d_out, int out_size)
{
    const float* logits = (const float*)d_in[0];
    float* out = (float*)d_out;
    const int n_seg = out_size;                  // 32768

    const int threads = WPB * 32;                // 64
    const int blocks = (n_seg + SEG_PER_BLOCK - 1) / SEG_PER_BLOCK;   // 4096
    rmloss_kernel<<<blocks, threads>>>(logits, out, n_seg);
}